// round 2
// baseline (speedup 1.0000x reference)
#include <cuda_runtime.h>
#include <math.h>

// Problem constants
#define CB 16
#define CS 512
#define CH 768
#define CT 2
#define CN 32
#define CL 64
#define CE 8
#define CD 128
#define CA 128

// ---------------- scratch (device globals; no allocation allowed) ----------------
__device__ float g_kbuf[CB*CT*CN*CL*CD];       // 33.5 MB  neighbor k projections
__device__ float g_msgs[CB*CT*CN*CE*CH];       // 25 MB    per-neighbor messages
__device__ float g_score[CB*CT*CN];
__device__ float g_c1[CB*CT];                  // wf . Wa[0:A]
__device__ float g_qe[CB*CT*CE*CD];            // entity-span q
__device__ float g_x[CB*CS*CH];                // updated sequence
__device__ float g_q2[CB*CS*CD];
__device__ float g_k2[CB*CS*CD];
__device__ float g_v2[CB*CS*CH];
__device__ float g_s2[CB*CS*CS];               // 16 MB    attn logits

// ---------------- generic tiled SGEMM: C = alpha * A*B(^T) (+bias) ----------------
// A [M,K] row-major. TRANSB=0: B [K,N]; TRANSB=1: B [N,K] (computes A*B^T).
// Batched via blockIdx.z with element strides sA,sB,sC.
template<int TRANSB>
__global__ void gemm_kernel(const float* __restrict__ A, const float* __restrict__ Bm,
                            const float* __restrict__ bias, float* __restrict__ C,
                            int M, int N, int K, float alpha,
                            long long sA, long long sB, long long sC) {
    A  += (long long)blockIdx.z * sA;
    Bm += (long long)blockIdx.z * sB;
    C  += (long long)blockIdx.z * sC;
    const int BM = 64, BN = 64, BK = 16;
    __shared__ float As[BK][BM];
    __shared__ float Bs[BK][BN];
    int tid = threadIdx.x;            // 256 threads
    int tx = tid & 15, ty = tid >> 4;
    int row0 = blockIdx.y * BM + ty * 4;
    int col0 = blockIdx.x * BN + tx * 4;
    float acc[4][4] = {};
    for (int k0 = 0; k0 < K; k0 += BK) {
        #pragma unroll
        for (int j = 0; j < 4; j++) {
            int i = tid + j * 256;            // A tile 64x16
            int m = i >> 4, k = i & 15;
            int gm = blockIdx.y * BM + m;
            As[k][m] = (gm < M && (k0 + k) < K) ? A[(long long)gm * K + k0 + k] : 0.f;
        }
        if (!TRANSB) {
            #pragma unroll
            for (int j = 0; j < 4; j++) {
                int i = tid + j * 256;        // B tile 16x64
                int k = i >> 6, n = i & 63;
                int gn = blockIdx.x * BN + n;
                Bs[k][n] = (gn < N && (k0 + k) < K) ? Bm[(long long)(k0 + k) * N + gn] : 0.f;
            }
        } else {
            #pragma unroll
            for (int j = 0; j < 4; j++) {
                int i = tid + j * 256;        // B tile from [N,K]
                int n = i >> 4, k = i & 15;
                int gn = blockIdx.x * BN + n;
                Bs[k][n] = (gn < N && (k0 + k) < K) ? Bm[(long long)gn * K + k0 + k] : 0.f;
            }
        }
        __syncthreads();
        #pragma unroll
        for (int k = 0; k < BK; k++) {
            float a[4], b[4];
            #pragma unroll
            for (int i = 0; i < 4; i++) a[i] = As[k][ty * 4 + i];
            #pragma unroll
            for (int j = 0; j < 4; j++) b[j] = Bs[k][tx * 4 + j];
            #pragma unroll
            for (int i = 0; i < 4; i++)
                #pragma unroll
                for (int j = 0; j < 4; j++) acc[i][j] += a[i] * b[j];
        }
        __syncthreads();
    }
    #pragma unroll
    for (int i = 0; i < 4; i++) {
        int gm = row0 + i;
        if (gm >= M) continue;
        #pragma unroll
        for (int j = 0; j < 4; j++) {
            int gn = col0 + j;
            if (gn >= N) continue;
            float v = acc[i][j] * alpha;
            if (bias) v += bias[gn];
            C[(long long)gm * N + gn] = v;
        }
    }
}

// ---------------- stage A: entity features -> q, feas, c1 = wf.Wa_lo ----------------
__global__ void stageA_kernel(const float* __restrict__ xs, const int* __restrict__ spans,
                              const float* __restrict__ Wq, const float* __restrict__ bq,
                              const float* __restrict__ Ww, const float* __restrict__ bw,
                              const float* __restrict__ Wa) {
    int bt = blockIdx.x;          // B*T = 32 blocks
    int b = bt / CT;
    int tid = threadIdx.x;        // 256
    int span = spans[bt];
    __shared__ float s_e[CE * CH];    // 24 KB
    __shared__ float s_feas[CH];
    __shared__ float s_part[256];
    for (int i = tid; i < CE * CH; i += 256) {
        int e = i / CH, h = i % CH;
        s_e[i] = xs[((long long)b * CS + span + e) * CH + h];
    }
    __syncthreads();
    // q = e_fea @ Wq + bq
    for (int o = tid; o < CE * CD; o += 256) {
        int e = o / CD, d = o % CD;
        float acc = bq[d];
        for (int h = 0; h < CH; h++) acc += s_e[e * CH + h] * Wq[h * CD + d];
        g_qe[(bt * CE + e) * CD + d] = acc;
    }
    // feas = mean_e e_fea
    for (int h = tid; h < CH; h += 256) {
        float acc = 0.f;
        #pragma unroll
        for (int e = 0; e < CE; e++) acc += s_e[e * CH + h];
        s_feas[h] = acc * (1.0f / CE);
    }
    __syncthreads();
    // wf = feas@Ww + bw ; c1 = wf . Wa[0:A]
    float part = 0.f;
    if (tid < CA) {
        float acc = bw[tid];
        for (int h = 0; h < CH; h++) acc += s_feas[h] * Ww[h * CA + tid];
        part = acc * Wa[tid];
    }
    s_part[tid] = part;
    __syncthreads();
    for (int s = 128; s > 0; s >>= 1) {
        if (tid < s) s_part[tid] += s_part[tid + s];
        __syncthreads();
    }
    if (tid == 0) g_c1[bt] = s_part[0];
}

// ---------------- stage B: per-neighbor SDPA + messages + score ----------------
__global__ void stageB_kernel(const float* __restrict__ neigh, const float* __restrict__ dists,
                              const float* __restrict__ Ww, const float* __restrict__ bw,
                              const float* __restrict__ Wa, const float* __restrict__ ba,
                              const float* __restrict__ wb, const float* __restrict__ bb) {
    int bid = blockIdx.x;                 // B*T*N = 1024 blocks
    int bt = bid / CN, n = bid % CN;
    int tid = threadIdx.x;                // 256
    const float inv_sqrt_d = 0.08838834764831845f;  // 1/sqrt(128)

    __shared__ float s_q[CE][CD];         // 4 KB
    __shared__ float s_kc[CL][CD + 1];    // 33 KB, reused: k tile then neigh chunks
    __shared__ float s_attn[CE][CL];      // 2 KB
    __shared__ float s_pooled[CH];        // 3 KB
    __shared__ float s_red[256];

    // load q and k tile
    for (int i = tid; i < CE * CD; i += 256) s_q[i / CD][i % CD] = g_qe[bt * CE * CD + i];
    const long long kb = ((long long)bid) * CL * CD;
    for (int i = tid; i < CL * CD; i += 256) {
        int l = i >> 7, d = i & 127;
        s_kc[l][d] = g_kbuf[kb + i];
    }
    __syncthreads();

    // logits (scaled)
    for (int o = tid; o < CE * CL; o += 256) {
        int e = o / CL, l = o % CL;
        float acc = 0.f;
        #pragma unroll 8
        for (int d = 0; d < CD; d++) acc += s_q[e][d] * s_kc[l][d];
        s_attn[e][l] = acc * inv_sqrt_d;
    }
    __syncthreads();

    // softmax over l: one warp per row e
    {
        int w = tid >> 5, lane = tid & 31;
        if (w < CE) {
            float v1 = s_attn[w][lane], v2 = s_attn[w][lane + 32];
            float m = fmaxf(v1, v2);
            #pragma unroll
            for (int off = 16; off; off >>= 1) m = fmaxf(m, __shfl_xor_sync(0xffffffffu, m, off));
            float e1 = __expf(v1 - m), e2 = __expf(v2 - m);
            float s = e1 + e2;
            #pragma unroll
            for (int off = 16; off; off >>= 1) s += __shfl_xor_sync(0xffffffffu, s, off);
            float inv = 1.0f / s;
            s_attn[w][lane] = e1 * inv;
            s_attn[w][lane + 32] = e2 * inv;
        }
    }
    __syncthreads();

    // msgs = attn @ neigh, streamed in 6 chunks of 128 h; pooled = mean_e msgs
    const long long nb = ((long long)bid) * CL * CH;
    const long long mb = ((long long)bid) * CE * CH;
    for (int hc = 0; hc < CH; hc += 128) {
        for (int i = tid; i < CL * 128; i += 256) {
            int l = i >> 7, j = i & 127;
            s_kc[l][j] = neigh[nb + (long long)l * CH + hc + j];
        }
        __syncthreads();
        float local = 0.f;
        #pragma unroll
        for (int rep = 0; rep < 4; rep++) {
            int o = tid + rep * 256;          // o < 1024 = E*128
            int e = o >> 7, j = o & 127;
            float acc = 0.f;
            #pragma unroll 8
            for (int l = 0; l < CL; l++) acc += s_attn[e][l] * s_kc[l][j];
            g_msgs[mb + (long long)e * CH + hc + j] = acc;
            local += acc;
        }
        s_red[tid] = local;
        __syncthreads();
        if (tid < 128) s_pooled[hc + tid] = (s_red[tid] + s_red[tid + 128]) * (1.0f / CE);
        __syncthreads();
    }

    // wp = pooled@Ww + bw ; s2 = wp . Wa[A:2A] ; score
    float part = 0.f;
    if (tid < CA) {
        float acc = bw[tid];
        for (int h = 0; h < CH; h++) acc += s_pooled[h] * Ww[h * CA + tid];
        part = acc * Wa[CA + tid];
    }
    s_red[tid] = part;
    __syncthreads();
    for (int s = 128; s > 0; s >>= 1) {
        if (tid < s) s_red[tid] += s_red[tid + s];
        __syncthreads();
    }
    if (tid == 0) {
        float v = g_c1[bt] + s_red[0] + ba[0];
        v = (v > 0.f) ? v : 0.01f * v;                     // leaky_relu(0.01)
        v += dists[bt * CN + n] * wb[0] + bb[0];
        g_score[bt * CN + n] = 1.0f / (1.0f + __expf(-v)); // sigmoid
    }
}

// ---------------- copy xs -> x ----------------
__global__ void copy_kernel(const float* __restrict__ xs) {
    long long i = (long long)blockIdx.x * blockDim.x + threadIdx.x;
    const long long n4 = (long long)CB * CS * CH / 4;
    if (i < n4) reinterpret_cast<float4*>(g_x)[i] = reinterpret_cast<const float4*>(xs)[i];
}

// ---------------- scatter delta into spans (one t per launch -> no conflicts) ----------------
__global__ void scatter_kernel(const int* __restrict__ spans, int t) {
    int i = blockIdx.x * blockDim.x + threadIdx.x;   // over B*E*H
    if (i >= CB * CE * CH) return;
    int b = i / (CE * CH);
    int r = i % (CE * CH);
    int e = r / CH, h = r % CH;
    int bt = b * CT + t;
    float val = 0.f;
    const float* sc = &g_score[bt * CN];
    const float* ms = &g_msgs[(((long long)bt * CN) * CE + e) * CH + h];
    #pragma unroll 8
    for (int n = 0; n < CN; n++) val += sc[n] * ms[(long long)n * CE * CH];
    int span = spans[bt];
    g_x[((long long)b * CS + span + e) * CH + h] += val;
}

// ---------------- row softmax for s2 (rows of length 512) ----------------
__global__ void softmax_kernel() {
    int row = blockIdx.x;                 // B*S rows
    int tid = threadIdx.x;                // 256
    float* p = &g_s2[(long long)row * CS];
    __shared__ float s_red[256];
    float v1 = p[tid], v2 = p[tid + 256];
    float m = fmaxf(v1, v2);
    s_red[tid] = m;
    __syncthreads();
    for (int s = 128; s > 0; s >>= 1) { if (tid < s) s_red[tid] = fmaxf(s_red[tid], s_red[tid + s]); __syncthreads(); }
    m = s_red[0];
    __syncthreads();
    float e1 = __expf(v1 - m), e2 = __expf(v2 - m);
    s_red[tid] = e1 + e2;
    __syncthreads();
    for (int s = 128; s > 0; s >>= 1) { if (tid < s) s_red[tid] += s_red[tid + s]; __syncthreads(); }
    float inv = 1.0f / s_red[0];
    p[tid] = e1 * inv;
    p[tid + 256] = e2 * inv;
}

// ---------------- host ----------------
extern "C" void kernel_launch(void* const* d_in, const int* in_sizes, int n_in,
                              void* d_out, int out_size) {
    const float* xs    = (const float*)d_in[0];
    const float* neigh = (const float*)d_in[1];
    const float* dists = (const float*)d_in[2];
    const int*   spans = (const int*)d_in[3];
    const float* Wq = (const float*)d_in[4];
    const float* bq = (const float*)d_in[5];
    const float* Wk = (const float*)d_in[6];
    const float* bk = (const float*)d_in[7];
    const float* Wv = (const float*)d_in[8];
    const float* bv = (const float*)d_in[9];
    const float* Ww = (const float*)d_in[10];
    const float* bw = (const float*)d_in[11];
    const float* Wa = (const float*)d_in[12];
    const float* ba = (const float*)d_in[13];
    const float* wb = (const float*)d_in[14];
    const float* bb = (const float*)d_in[15];
    float* out = (float*)d_out;

    float *kbuf, *x, *q2, *k2, *v2, *s2;
    cudaGetSymbolAddress((void**)&kbuf, g_kbuf);
    cudaGetSymbolAddress((void**)&x,    g_x);
    cudaGetSymbolAddress((void**)&q2,   g_q2);
    cudaGetSymbolAddress((void**)&k2,   g_k2);
    cudaGetSymbolAddress((void**)&v2,   g_v2);
    cudaGetSymbolAddress((void**)&s2,   g_s2);

    const float inv_sqrt_d = 0.08838834764831845f;

    // stage A: entity q / feas / c1
    stageA_kernel<<<CB * CT, 256>>>(xs, spans, Wq, bq, Ww, bw, Wa);

    // k projection for all neighbor tokens: [65536,768] @ [768,128]
    {
        dim3 grid(CD / 64, (CB * CT * CN * CL) / 64, 1);
        gemm_kernel<0><<<grid, 256>>>(neigh, Wk, bk, kbuf,
                                      CB * CT * CN * CL, CD, CH, 1.0f, 0, 0, 0);
    }

    // per-neighbor SDPA + messages + scores
    stageB_kernel<<<CB * CT * CN, 256>>>(neigh, dists, Ww, bw, Wa, ba, wb, bb);

    // x = xs ; then add delta into spans (t=0, t=1 sequentially: deterministic)
    copy_kernel<<<(CB * CS * CH / 4 + 255) / 256, 256>>>(xs);
    scatter_kernel<<<(CB * CE * CH + 255) / 256, 256>>>(spans, 0);
    scatter_kernel<<<(CB * CE * CH + 255) / 256, 256>>>(spans, 1);

    // final projections
    {
        dim3 grid(CD / 64, (CB * CS) / 64, 1);
        gemm_kernel<0><<<grid, 256>>>(x, Wq, bq, q2, CB * CS, CD, CH, 1.0f, 0, 0, 0);
        gemm_kernel<0><<<grid, 256>>>(x, Wk, bk, k2, CB * CS, CD, CH, 1.0f, 0, 0, 0);
    }
    {
        dim3 grid(CH / 64, (CB * CS) / 64, 1);
        gemm_kernel<0><<<grid, 256>>>(x, Wv, bv, v2, CB * CS, CH, CH, 1.0f, 0, 0, 0);
    }

    // s2 = q2 @ k2^T * inv_sqrt_d  (batched over B)
    {
        dim3 grid(CS / 64, CS / 64, CB);
        gemm_kernel<1><<<grid, 256>>>(q2, k2, nullptr, s2, CS, CS, CD, inv_sqrt_d,
                                      (long long)CS * CD, (long long)CS * CD, (long long)CS * CS);
    }

    // row softmax
    softmax_kernel<<<CB * CS, 256>>>();

    // out = softmax(s2) @ v2  (batched over B)
    {
        dim3 grid(CH / 64, CS / 64, CB);
        gemm_kernel<0><<<grid, 256>>>(s2, v2, nullptr, out, CS, CH, CS, 1.0f,
                                      (long long)CS * CS, (long long)CS * CH, (long long)CS * CH);
    }
}

// round 4
// speedup vs baseline: 1.7821x; 1.7821x over previous
#include <cuda_runtime.h>
#include <math.h>
#include <stdint.h>

// Problem constants
#define CB 16
#define CS 512
#define CH 768
#define CT 2
#define CN 32
#define CL 64
#define CE 8
#define CD 128
#define CA 128

// ---------------- scratch (device globals; no allocation allowed) ----------------
__device__ float g_kbuf[CB*CT*CN*CL*CD];       // neighbor k projections
__device__ float g_msgs[CB*CT*CN*CE*CH];       // per-neighbor messages
__device__ float g_score[CB*CT*CN];
__device__ float g_c1[CB*CT];
__device__ float g_qe[CB*CT*CE*CD];
__device__ float g_x[CB*CS*CH];
__device__ float g_q2[CB*CS*CD];
__device__ float g_k2[CB*CS*CD];
__device__ float g_v2[CB*CS*CH];
__device__ float g_v2T[CB*CS*CH];              // per-batch transposed V
__device__ float g_s2[CB*CS*CS];
__device__ float g_wqT[CD*CH];                 // Wq^T [128,768]
__device__ float g_wkT[CD*CH];
__device__ float g_wvT[CH*CH];

// ================= tf32 mma.sync GEMM: C = alpha * A @ B^T (+bias) =================
// A [M,K] row-major, B [N,K] row-major, C [M,N]. M,N mult of 128, K mult of 32.
// Batched via blockIdx.z with element strides sA,sB,sC. 256 threads (8 warps, 4x2).
//
// SMEM tiles stored in *fragment order* for m16n8k8:
//   A: [4 kstep][8 mtile][32 lane][4]  (a0..a3 for that lane)
//   B: [4 kstep][16 ntile][32 lane][2] (b0..b1 for that lane)
// so fragment fetch = 1x LDS.128 (A) / 1x LDS.64 (B), conflict-free.

#define GE_SMEM_BYTES 65536   // 2 buffers x (16KB A + 16KB B)

__device__ __forceinline__ void mma_tf32(float c[4], const uint32_t a[4], const uint32_t b[2]) {
    asm volatile(
        "mma.sync.aligned.m16n8k8.row.col.f32.tf32.tf32.f32 "
        "{%0,%1,%2,%3}, {%4,%5,%6,%7}, {%8,%9}, {%0,%1,%2,%3};"
        : "+f"(c[0]), "+f"(c[1]), "+f"(c[2]), "+f"(c[3])
        : "r"(a[0]), "r"(a[1]), "r"(a[2]), "r"(a[3]), "r"(b[0]), "r"(b[1]));
}

// load a 128x32 tf32 tile from GMEM into regs (rounded to tf32)
__device__ __forceinline__ void tile_ldg(const float* __restrict__ p, int ldk, int tid, float4 r[4]) {
    #pragma unroll
    for (int j = 0; j < 4; j++) {
        int f = j * 256 + tid;
        int row = f >> 3, c4 = f & 7;
        float4 v = *reinterpret_cast<const float4*>(p + (long long)row * ldk + c4 * 4);
        asm volatile("cvt.rna.tf32.f32 %0, %0;" : "+r"(*(uint32_t*)&v.x));
        asm volatile("cvt.rna.tf32.f32 %0, %0;" : "+r"(*(uint32_t*)&v.y));
        asm volatile("cvt.rna.tf32.f32 %0, %0;" : "+r"(*(uint32_t*)&v.z));
        asm volatile("cvt.rna.tf32.f32 %0, %0;" : "+r"(*(uint32_t*)&v.w));
        r[j] = v;
    }
}

// scatter tile regs into A-fragment-order SMEM
__device__ __forceinline__ void sts_fragA(float* sm, int tid, const float4 r[4]) {
    #pragma unroll
    for (int j = 0; j < 4; j++) {
        int f = j * 256 + tid;
        int row = f >> 3, c4 = f & 7;       // row 0..127, col group (4 k) 0..7
        int ks = c4 >> 1;                   // k8 step
        int jfrag = ((row >> 3) & 1) + ((c4 & 1) << 1);
        int mt = row >> 4, g = row & 7;
        float* base = sm + (((ks * 8 + mt) * 32 + g * 4) << 2) + jfrag;
        const float* v = reinterpret_cast<const float*>(&r[j]);
        #pragma unroll
        for (int t = 0; t < 4; t++) base[t << 2] = v[t];
    }
}

// scatter tile regs into B-fragment-order SMEM
__device__ __forceinline__ void sts_fragB(float* sm, int tid, const float4 r[4]) {
    #pragma unroll
    for (int j = 0; j < 4; j++) {
        int f = j * 256 + tid;
        int row = f >> 3, c4 = f & 7;       // row = n 0..127
        int ks = c4 >> 1;
        int jfrag = c4 & 1;
        int nt = row >> 3, g = row & 7;
        float* base = sm + (((ks * 16 + nt) * 32 + g * 4) << 1) + jfrag;
        const float* v = reinterpret_cast<const float*>(&r[j]);
        #pragma unroll
        for (int t = 0; t < 4; t++) base[t << 1] = v[t];
    }
}

__global__ void __launch_bounds__(256, 1)
mm_gemm_kernel(const float* __restrict__ A, const float* __restrict__ B,
               const float* __restrict__ bias, float* __restrict__ C,
               int M, int N, int K, float alpha,
               long long sA, long long sB, long long sC)
{
    extern __shared__ float smem[];
    // buffers: [buf][A(4096) | B(4096)]
    float* smA[2] = { smem,          smem + 8192 };
    float* smB[2] = { smem + 4096,   smem + 12288 };

    int tid = threadIdx.x;
    int wid = tid >> 5, lane = tid & 31;
    int warpM = wid & 3;          // 0..3  -> 32-row slab
    int warpN = wid >> 2;         // 0..1  -> 64-col slab

    const float* Ab = A + (long long)blockIdx.z * sA + (long long)(blockIdx.y * 128) * K;
    const float* Bb = B + (long long)blockIdx.z * sB + (long long)(blockIdx.x * 128) * K;

    float acc[2][8][4];
    #pragma unroll
    for (int i = 0; i < 2; i++)
        #pragma unroll
        for (int j = 0; j < 8; j++)
            #pragma unroll
            for (int c = 0; c < 4; c++) acc[i][j][c] = 0.f;

    int nch = K >> 5;
    float4 ra[4], rb[4];
    tile_ldg(Ab, K, tid, ra);
    tile_ldg(Bb, K, tid, rb);
    sts_fragA(smA[0], tid, ra);
    sts_fragB(smB[0], tid, rb);
    __syncthreads();

    for (int i = 0; i < nch; i++) {
        int buf = i & 1;
        if (i + 1 < nch) {
            tile_ldg(Ab + (i + 1) * 32, K, tid, ra);
            tile_ldg(Bb + (i + 1) * 32, K, tid, rb);
        }
        const float* fA = smA[buf] + ((warpM * 2) * 32 + lane) * 4;   // mtile base for this warp
        const float* fB = smB[buf] + ((warpN * 8) * 32 + lane) * 2;
        #pragma unroll
        for (int ks = 0; ks < 4; ks++) {
            uint32_t afr[2][4];
            #pragma unroll
            for (int mt = 0; mt < 2; mt++) {
                float4 v = *reinterpret_cast<const float4*>(fA + (ks * 8 + mt) * 128);
                afr[mt][0] = __float_as_uint(v.x); afr[mt][1] = __float_as_uint(v.y);
                afr[mt][2] = __float_as_uint(v.z); afr[mt][3] = __float_as_uint(v.w);
            }
            #pragma unroll
            for (int nt = 0; nt < 8; nt++) {
                float2 v = *reinterpret_cast<const float2*>(fB + (ks * 16 + nt) * 64);
                uint32_t bfr[2] = { __float_as_uint(v.x), __float_as_uint(v.y) };
                mma_tf32(acc[0][nt], afr[0], bfr);
                mma_tf32(acc[1][nt], afr[1], bfr);
            }
        }
        __syncthreads();
        if (i + 1 < nch) {
            sts_fragA(smA[buf ^ 1], tid, ra);
            sts_fragB(smB[buf ^ 1], tid, rb);
            __syncthreads();
        }
    }

    // epilogue: thread (g = lane>>2, t = lane&3)
    int g = lane >> 2, t = lane & 3;
    long long crow0 = (long long)(blockIdx.y * 128 + warpM * 32 + g);
    int col0 = blockIdx.x * 128 + warpN * 64 + t * 2;
    float* Cb = C + (long long)blockIdx.z * sC;
    #pragma unroll
    for (int mt = 0; mt < 2; mt++) {
        #pragma unroll
        for (int nt = 0; nt < 8; nt++) {
            int cc = col0 + nt * 8;
            float bx = 0.f, by = 0.f;
            if (bias) { bx = bias[cc]; by = bias[cc + 1]; }
            long long r0 = crow0 + mt * 16;
            float2 v0 = { acc[mt][nt][0] * alpha + bx, acc[mt][nt][1] * alpha + by };
            float2 v1 = { acc[mt][nt][2] * alpha + bx, acc[mt][nt][3] * alpha + by };
            *reinterpret_cast<float2*>(Cb + r0 * N + cc) = v0;
            *reinterpret_cast<float2*>(Cb + (r0 + 8) * N + cc) = v1;
        }
    }
}

// ---------------- transpose: dst[C,R] = src[R,C]^T, batched ----------------
__global__ void transpose_kernel(const float* __restrict__ src, float* __restrict__ dst,
                                 int R, int C, long long sS, long long sD) {
    __shared__ float t[32][33];
    src += (long long)blockIdx.z * sS;
    dst += (long long)blockIdx.z * sD;
    int r0 = blockIdx.y * 32, c0 = blockIdx.x * 32;
    int x = threadIdx.x, y = threadIdx.y;     // 32 x 8
    #pragma unroll
    for (int j = 0; j < 32; j += 8)
        if (r0 + y + j < R && c0 + x < C)
            t[y + j][x] = src[(long long)(r0 + y + j) * C + c0 + x];
    __syncthreads();
    #pragma unroll
    for (int j = 0; j < 32; j += 8)
        if (c0 + y + j < C && r0 + x < R)
            dst[(long long)(c0 + y + j) * R + r0 + x] = t[x][y + j];
}

// ---------------- stage A: entity features -> q, feas, c1 = wf.Wa_lo ----------------
__global__ void stageA_kernel(const float* __restrict__ xs, const int* __restrict__ spans,
                              const float* __restrict__ Wq, const float* __restrict__ bq,
                              const float* __restrict__ Ww, const float* __restrict__ bw,
                              const float* __restrict__ Wa) {
    int bt = blockIdx.x;
    int b = bt / CT;
    int tid = threadIdx.x;
    int span = spans[bt];
    __shared__ float s_e[CE * CH];
    __shared__ float s_feas[CH];
    __shared__ float s_part[256];
    for (int i = tid; i < CE * CH; i += 256) {
        int e = i / CH, h = i % CH;
        s_e[i] = xs[((long long)b * CS + span + e) * CH + h];
    }
    __syncthreads();
    for (int o = tid; o < CE * CD; o += 256) {
        int e = o / CD, d = o % CD;
        float acc = bq[d];
        for (int h = 0; h < CH; h++) acc += s_e[e * CH + h] * Wq[h * CD + d];
        g_qe[(bt * CE + e) * CD + d] = acc;
    }
    for (int h = tid; h < CH; h += 256) {
        float acc = 0.f;
        #pragma unroll
        for (int e = 0; e < CE; e++) acc += s_e[e * CH + h];
        s_feas[h] = acc * (1.0f / CE);
    }
    __syncthreads();
    float part = 0.f;
    if (tid < CA) {
        float acc = bw[tid];
        for (int h = 0; h < CH; h++) acc += s_feas[h] * Ww[h * CA + tid];
        part = acc * Wa[tid];
    }
    s_part[tid] = part;
    __syncthreads();
    for (int s = 128; s > 0; s >>= 1) {
        if (tid < s) s_part[tid] += s_part[tid + s];
        __syncthreads();
    }
    if (tid == 0) g_c1[bt] = s_part[0];
}

// ---------------- stage B: per-neighbor SDPA + messages + score ----------------
__global__ void stageB_kernel(const float* __restrict__ neigh, const float* __restrict__ dists,
                              const float* __restrict__ Ww, const float* __restrict__ bw,
                              const float* __restrict__ Wa, const float* __restrict__ ba,
                              const float* __restrict__ wb, const float* __restrict__ bb) {
    int bid = blockIdx.x;
    int bt = bid / CN, n = bid % CN;
    int tid = threadIdx.x;
    const float inv_sqrt_d = 0.08838834764831845f;

    __shared__ float s_q[CE][CD];
    __shared__ float s_kc[CL][CD + 1];
    __shared__ float s_attn[CE][CL];
    __shared__ float s_pooled[CH];
    __shared__ float s_red[256];

    for (int i = tid; i < CE * CD; i += 256) s_q[i / CD][i % CD] = g_qe[bt * CE * CD + i];
    const long long kb = ((long long)bid) * CL * CD;
    for (int i = tid; i < CL * CD; i += 256) {
        int l = i >> 7, d = i & 127;
        s_kc[l][d] = g_kbuf[kb + i];
    }
    __syncthreads();

    for (int o = tid; o < CE * CL; o += 256) {
        int e = o / CL, l = o % CL;
        float acc = 0.f;
        #pragma unroll 8
        for (int d = 0; d < CD; d++) acc += s_q[e][d] * s_kc[l][d];
        s_attn[e][l] = acc * inv_sqrt_d;
    }
    __syncthreads();

    {
        int w = tid >> 5, lane = tid & 31;
        if (w < CE) {
            float v1 = s_attn[w][lane], v2 = s_attn[w][lane + 32];
            float m = fmaxf(v1, v2);
            #pragma unroll
            for (int off = 16; off; off >>= 1) m = fmaxf(m, __shfl_xor_sync(0xffffffffu, m, off));
            float e1 = __expf(v1 - m), e2 = __expf(v2 - m);
            float s = e1 + e2;
            #pragma unroll
            for (int off = 16; off; off >>= 1) s += __shfl_xor_sync(0xffffffffu, s, off);
            float inv = 1.0f / s;
            s_attn[w][lane] = e1 * inv;
            s_attn[w][lane + 32] = e2 * inv;
        }
    }
    __syncthreads();

    const long long nb = ((long long)bid) * CL * CH;
    const long long mb = ((long long)bid) * CE * CH;
    for (int hc = 0; hc < CH; hc += 128) {
        for (int i = tid; i < CL * 128; i += 256) {
            int l = i >> 7, j = i & 127;
            s_kc[l][j] = neigh[nb + (long long)l * CH + hc + j];
        }
        __syncthreads();
        float local = 0.f;
        #pragma unroll
        for (int rep = 0; rep < 4; rep++) {
            int o = tid + rep * 256;
            int e = o >> 7, j = o & 127;
            float acc = 0.f;
            #pragma unroll 8
            for (int l = 0; l < CL; l++) acc += s_attn[e][l] * s_kc[l][j];
            g_msgs[mb + (long long)e * CH + hc + j] = acc;
            local += acc;
        }
        s_red[tid] = local;
        __syncthreads();
        if (tid < 128) s_pooled[hc + tid] = (s_red[tid] + s_red[tid + 128]) * (1.0f / CE);
        __syncthreads();
    }

    float part = 0.f;
    if (tid < CA) {
        float acc = bw[tid];
        for (int h = 0; h < CH; h++) acc += s_pooled[h] * Ww[h * CA + tid];
        part = acc * Wa[CA + tid];
    }
    s_red[tid] = part;
    __syncthreads();
    for (int s = 128; s > 0; s >>= 1) {
        if (tid < s) s_red[tid] += s_red[tid + s];
        __syncthreads();
    }
    if (tid == 0) {
        float v = g_c1[bt] + s_red[0] + ba[0];
        v = (v > 0.f) ? v : 0.01f * v;
        v += dists[bt * CN + n] * wb[0] + bb[0];
        g_score[bt * CN + n] = 1.0f / (1.0f + __expf(-v));
    }
}

// ---------------- copy xs -> x ----------------
__global__ void copy_kernel(const float* __restrict__ xs) {
    long long i = (long long)blockIdx.x * blockDim.x + threadIdx.x;
    const long long n4 = (long long)CB * CS * CH / 4;
    if (i < n4) reinterpret_cast<float4*>(g_x)[i] = reinterpret_cast<const float4*>(xs)[i];
}

// ---------------- scatter delta into spans (one t per launch) ----------------
__global__ void scatter_kernel(const int* __restrict__ spans, int t) {
    int i = blockIdx.x * blockDim.x + threadIdx.x;
    if (i >= CB * CE * CH) return;
    int b = i / (CE * CH);
    int r = i % (CE * CH);
    int e = r / CH, h = r % CH;
    int bt = b * CT + t;
    float val = 0.f;
    const float* sc = &g_score[bt * CN];
    const float* ms = &g_msgs[(((long long)bt * CN) * CE + e) * CH + h];
    #pragma unroll 8
    for (int n = 0; n < CN; n++) val += sc[n] * ms[(long long)n * CE * CH];
    int span = spans[bt];
    g_x[((long long)b * CS + span + e) * CH + h] += val;
}

// ---------------- row softmax for s2 ----------------
__global__ void softmax_kernel() {
    int row = blockIdx.x;
    int tid = threadIdx.x;
    float* p = &g_s2[(long long)row * CS];
    __shared__ float s_red[256];
    float v1 = p[tid], v2 = p[tid + 256];
    float m = fmaxf(v1, v2);
    s_red[tid] = m;
    __syncthreads();
    for (int s = 128; s > 0; s >>= 1) { if (tid < s) s_red[tid] = fmaxf(s_red[tid], s_red[tid + s]); __syncthreads(); }
    m = s_red[0];
    __syncthreads();
    float e1 = __expf(v1 - m), e2 = __expf(v2 - m);
    s_red[tid] = e1 + e2;
    __syncthreads();
    for (int s = 128; s > 0; s >>= 1) { if (tid < s) s_red[tid] += s_red[tid + s]; __syncthreads(); }
    float inv = 1.0f / s_red[0];
    p[tid] = e1 * inv;
    p[tid + 256] = e2 * inv;
}

// ---------------- host ----------------
extern "C" void kernel_launch(void* const* d_in, const int* in_sizes, int n_in,
                              void* d_out, int out_size) {
    const float* xs    = (const float*)d_in[0];
    const float* neigh = (const float*)d_in[1];
    const float* dists = (const float*)d_in[2];
    const int*   spans = (const int*)d_in[3];
    const float* Wq = (const float*)d_in[4];
    const float* bq = (const float*)d_in[5];
    const float* Wk = (const float*)d_in[6];
    const float* bk = (const float*)d_in[7];
    const float* Wv = (const float*)d_in[8];
    const float* bv = (const float*)d_in[9];
    const float* Ww = (const float*)d_in[10];
    const float* bw = (const float*)d_in[11];
    const float* Wa = (const float*)d_in[12];
    const float* ba = (const float*)d_in[13];
    const float* wb = (const float*)d_in[14];
    const float* bb = (const float*)d_in[15];
    float* out = (float*)d_out;

    float *kbuf, *x, *q2, *k2, *v2, *v2T, *s2, *wqT, *wkT, *wvT;
    cudaGetSymbolAddress((void**)&kbuf, g_kbuf);
    cudaGetSymbolAddress((void**)&x,    g_x);
    cudaGetSymbolAddress((void**)&q2,   g_q2);
    cudaGetSymbolAddress((void**)&k2,   g_k2);
    cudaGetSymbolAddress((void**)&v2,   g_v2);
    cudaGetSymbolAddress((void**)&v2T,  g_v2T);
    cudaGetSymbolAddress((void**)&s2,   g_s2);
    cudaGetSymbolAddress((void**)&wqT,  g_wqT);
    cudaGetSymbolAddress((void**)&wkT,  g_wkT);
    cudaGetSymbolAddress((void**)&wvT,  g_wvT);

    cudaFuncSetAttribute(mm_gemm_kernel, cudaFuncAttributeMaxDynamicSharedMemorySize, GE_SMEM_BYTES);

    const float inv_sqrt_d = 0.08838834764831845f;
    dim3 tb(32, 8);

    // weight transposes: W[K,N] -> W^T[N,K]
    transpose_kernel<<<dim3(4, 24, 1), tb>>>(Wq, wqT, CH, CD, 0, 0);
    transpose_kernel<<<dim3(4, 24, 1), tb>>>(Wk, wkT, CH, CD, 0, 0);
    transpose_kernel<<<dim3(24, 24, 1), tb>>>(Wv, wvT, CH, CH, 0, 0);

    // stage A: entity q / feas / c1
    stageA_kernel<<<CB * CT, 256>>>(xs, spans, Wq, bq, Ww, bw, Wa);

    // k projection: [65536,768] @ WkT^T -> [65536,128]
    mm_gemm_kernel<<<dim3(1, 512, 1), 256, GE_SMEM_BYTES>>>(
        neigh, wkT, bk, kbuf, CB * CT * CN * CL, CD, CH, 1.0f, 0, 0, 0);

    // per-neighbor SDPA + messages + scores
    stageB_kernel<<<CB * CT * CN, 256>>>(neigh, dists, Ww, bw, Wa, ba, wb, bb);

    // x = xs; scatter deltas (t=0, t=1 sequential: deterministic)
    copy_kernel<<<(CB * CS * CH / 4 + 255) / 256, 256>>>(xs);
    scatter_kernel<<<(CB * CE * CH + 255) / 256, 256>>>(spans, 0);
    scatter_kernel<<<(CB * CE * CH + 255) / 256, 256>>>(spans, 1);

    // final projections
    mm_gemm_kernel<<<dim3(1, 64, 1), 256, GE_SMEM_BYTES>>>(
        x, wqT, bq, q2, CB * CS, CD, CH, 1.0f, 0, 0, 0);
    mm_gemm_kernel<<<dim3(1, 64, 1), 256, GE_SMEM_BYTES>>>(
        x, wkT, bk, k2, CB * CS, CD, CH, 1.0f, 0, 0, 0);
    mm_gemm_kernel<<<dim3(6, 64, 1), 256, GE_SMEM_BYTES>>>(
        x, wvT, bv, v2, CB * CS, CH, CH, 1.0f, 0, 0, 0);

    // transpose v2 per batch: [512,768] -> [768,512]
    transpose_kernel<<<dim3(24, 16, CB), tb>>>(v2, v2T, CS, CH,
                                               (long long)CS * CH, (long long)CS * CH);

    // s2 = q2 @ k2^T * inv_sqrt_d (batched)
    mm_gemm_kernel<<<dim3(4, 4, CB), 256, GE_SMEM_BYTES>>>(
        q2, k2, nullptr, s2, CS, CS, CD, inv_sqrt_d,
        (long long)CS * CD, (long long)CS * CD, (long long)CS * CS);

    softmax_kernel<<<CB * CS, 256>>>();

    // out = softmax(s2) @ v2  (B operand = v2T [768,512], batched)
    mm_gemm_kernel<<<dim3(6, 4, CB), 256, GE_SMEM_BYTES>>>(
        s2, v2T, nullptr, out, CS, CH, CS, 1.0f,
        (long long)CS * CS, (long long)CH * CS, (long long)CS * CH);
}

// round 6
// speedup vs baseline: 1.9705x; 1.1057x over previous
#include <cuda_runtime.h>
#include <math.h>
#include <stdint.h>

// Problem constants
#define CB 16
#define CS 512
#define CH 768
#define CT 2
#define CN 32
#define CL 64
#define CE 8
#define CD 128
#define CA 128

// ---------------- scratch (device globals; no allocation allowed) ----------------
__device__ float g_kbuf[CB*CT*CN*CL*CD];       // neighbor k projections
__device__ float g_msgs[CB*CT*CN*CE*CH];       // per-neighbor messages
__device__ float g_score[CB*CT*CN];
__device__ float g_c1[CB*CT];
__device__ float g_qe[CB*CT*CE*CD];
__device__ float g_efea[CB*CT*CE*CH];          // gathered entity span features [256,768]
__device__ float g_x[CB*CS*CH];
__device__ float g_qk2[CB*CS*2*CD];            // fused q2|k2 [B*S, 256]
__device__ float g_v2T[CB*CH*CS];              // v2 transposed per batch [B][768][512]
__device__ float g_s2[CB*CS*CS];
__device__ float g_wqkT[2*CD*CH];              // [WqT; WkT] [256,768]
__device__ float g_wvT[CH*CH];
__device__ float g_bqk[2*CD];

// ================= tf32 mma.sync GEMM: C = alpha * A @ B^T (+bias) =================
// A [M,K] rows lda, B [N,K] rows ldb, C [M,N] rows ldc. M,N mult 128, K mult 32.
// bias_mode: 0 none, 1 per-col, 2 per-row. Batched via blockIdx.z (strides sA,sB,sC).
// 256 threads (8 warps, 4x2). SMEM tiles in m16n8k8 fragment order.

#define GE_SMEM_BYTES 65536

__device__ __forceinline__ void mma_tf32(float c[4], const uint32_t a[4], const uint32_t b[2]) {
    asm volatile(
        "mma.sync.aligned.m16n8k8.row.col.f32.tf32.tf32.f32 "
        "{%0,%1,%2,%3}, {%4,%5,%6,%7}, {%8,%9}, {%0,%1,%2,%3};"
        : "+f"(c[0]), "+f"(c[1]), "+f"(c[2]), "+f"(c[3])
        : "r"(a[0]), "r"(a[1]), "r"(a[2]), "r"(a[3]), "r"(b[0]), "r"(b[1]));
}

__device__ __forceinline__ void tile_ldg(const float* __restrict__ p, int lda, int tid, float4 r[4]) {
    #pragma unroll
    for (int j = 0; j < 4; j++) {
        int f = j * 256 + tid;
        int row = f >> 3, c4 = f & 7;
        float4 v = *reinterpret_cast<const float4*>(p + (long long)row * lda + c4 * 4);
        asm volatile("cvt.rna.tf32.f32 %0, %0;" : "+r"(*(uint32_t*)&v.x));
        asm volatile("cvt.rna.tf32.f32 %0, %0;" : "+r"(*(uint32_t*)&v.y));
        asm volatile("cvt.rna.tf32.f32 %0, %0;" : "+r"(*(uint32_t*)&v.z));
        asm volatile("cvt.rna.tf32.f32 %0, %0;" : "+r"(*(uint32_t*)&v.w));
        r[j] = v;
    }
}

__device__ __forceinline__ void sts_fragA(float* sm, int tid, const float4 r[4]) {
    #pragma unroll
    for (int j = 0; j < 4; j++) {
        int f = j * 256 + tid;
        int row = f >> 3, c4 = f & 7;
        int ks = c4 >> 1;
        int jfrag = ((row >> 3) & 1) + ((c4 & 1) << 1);
        int mt = row >> 4, g = row & 7;
        float* base = sm + (((ks * 8 + mt) * 32 + g * 4) << 2) + jfrag;
        const float* v = reinterpret_cast<const float*>(&r[j]);
        #pragma unroll
        for (int t = 0; t < 4; t++) base[t << 2] = v[t];
    }
}

__device__ __forceinline__ void sts_fragB(float* sm, int tid, const float4 r[4]) {
    #pragma unroll
    for (int j = 0; j < 4; j++) {
        int f = j * 256 + tid;
        int row = f >> 3, c4 = f & 7;
        int ks = c4 >> 1;
        int jfrag = c4 & 1;
        int nt = row >> 3, g = row & 7;
        float* base = sm + (((ks * 16 + nt) * 32 + g * 4) << 1) + jfrag;
        const float* v = reinterpret_cast<const float*>(&r[j]);
        #pragma unroll
        for (int t = 0; t < 4; t++) base[t << 1] = v[t];
    }
}

__global__ void __launch_bounds__(256)
mm_gemm_kernel(const float* __restrict__ A, const float* __restrict__ B,
               const float* __restrict__ bias, float* __restrict__ C,
               int M, int N, int K, float alpha,
               int lda, int ldb, int ldc, int bias_mode,
               long long sA, long long sB, long long sC)
{
    extern __shared__ float smem[];
    float* smA[2] = { smem,          smem + 8192 };
    float* smB[2] = { smem + 4096,   smem + 12288 };

    int tid = threadIdx.x;
    int wid = tid >> 5, lane = tid & 31;
    int warpM = wid & 3;
    int warpN = wid >> 2;

    const float* Ab = A + (long long)blockIdx.z * sA + (long long)(blockIdx.y * 128) * lda;
    const float* Bb = B + (long long)blockIdx.z * sB + (long long)(blockIdx.x * 128) * ldb;

    float acc[2][8][4];
    #pragma unroll
    for (int i = 0; i < 2; i++)
        #pragma unroll
        for (int j = 0; j < 8; j++)
            #pragma unroll
            for (int c = 0; c < 4; c++) acc[i][j][c] = 0.f;

    int nch = K >> 5;
    float4 ra[4], rb[4];
    tile_ldg(Ab, lda, tid, ra);
    tile_ldg(Bb, ldb, tid, rb);
    sts_fragA(smA[0], tid, ra);
    sts_fragB(smB[0], tid, rb);
    __syncthreads();

    for (int i = 0; i < nch; i++) {
        int buf = i & 1;
        if (i + 1 < nch) {
            tile_ldg(Ab + (i + 1) * 32, lda, tid, ra);
            tile_ldg(Bb + (i + 1) * 32, ldb, tid, rb);
        }
        const float* fA = smA[buf] + ((warpM * 2) * 32 + lane) * 4;
        const float* fB = smB[buf] + ((warpN * 8) * 32 + lane) * 2;
        #pragma unroll
        for (int ks = 0; ks < 4; ks++) {
            uint32_t afr[2][4];
            #pragma unroll
            for (int mt = 0; mt < 2; mt++) {
                float4 v = *reinterpret_cast<const float4*>(fA + (ks * 8 + mt) * 128);
                afr[mt][0] = __float_as_uint(v.x); afr[mt][1] = __float_as_uint(v.y);
                afr[mt][2] = __float_as_uint(v.z); afr[mt][3] = __float_as_uint(v.w);
            }
            #pragma unroll
            for (int nt = 0; nt < 8; nt++) {
                float2 v = *reinterpret_cast<const float2*>(fB + (ks * 16 + nt) * 64);
                uint32_t bfr[2] = { __float_as_uint(v.x), __float_as_uint(v.y) };
                mma_tf32(acc[0][nt], afr[0], bfr);
                mma_tf32(acc[1][nt], afr[1], bfr);
            }
        }
        __syncthreads();
        if (i + 1 < nch) {
            sts_fragA(smA[buf ^ 1], tid, ra);
            sts_fragB(smB[buf ^ 1], tid, rb);
            __syncthreads();
        }
    }

    int g = lane >> 2, t = lane & 3;
    long long crow0 = (long long)(blockIdx.y * 128 + warpM * 32 + g);
    int col0 = blockIdx.x * 128 + warpN * 64 + t * 2;
    float* Cb = C + (long long)blockIdx.z * sC;
    #pragma unroll
    for (int mt = 0; mt < 2; mt++) {
        long long r0 = crow0 + mt * 16;
        float br0 = 0.f, br1 = 0.f;
        if (bias_mode == 2) { br0 = bias[r0]; br1 = bias[r0 + 8]; }
        #pragma unroll
        for (int nt = 0; nt < 8; nt++) {
            int cc = col0 + nt * 8;
            float bcx = 0.f, bcy = 0.f;
            if (bias_mode == 1) { bcx = bias[cc]; bcy = bias[cc + 1]; }
            float2 v0 = { acc[mt][nt][0] * alpha + bcx + br0, acc[mt][nt][1] * alpha + bcy + br0 };
            float2 v1 = { acc[mt][nt][2] * alpha + bcx + br1, acc[mt][nt][3] * alpha + bcy + br1 };
            *reinterpret_cast<float2*>(Cb + r0 * ldc + cc) = v0;
            *reinterpret_cast<float2*>(Cb + (r0 + 8) * ldc + cc) = v1;
        }
    }
}

// ---------------- transpose: dst[C,R] = src[R,C]^T ----------------
__global__ void transpose_kernel(const float* __restrict__ src, float* __restrict__ dst,
                                 int R, int C) {
    __shared__ float t[32][33];
    int r0 = blockIdx.y * 32, c0 = blockIdx.x * 32;
    int x = threadIdx.x, y = threadIdx.y;     // 32 x 8
    #pragma unroll
    for (int j = 0; j < 32; j += 8)
        if (r0 + y + j < R && c0 + x < C)
            t[y + j][x] = src[(long long)(r0 + y + j) * C + c0 + x];
    __syncthreads();
    #pragma unroll
    for (int j = 0; j < 32; j += 8)
        if (c0 + y + j < C && r0 + x < R)
            dst[(long long)(c0 + y + j) * R + r0 + x] = t[x][y + j];
}

// ---------------- pack [bq;bk] ----------------
__global__ void pack_bqk_kernel(const float* __restrict__ bq, const float* __restrict__ bk) {
    int i = threadIdx.x;
    g_bqk[i] = (i < CD) ? bq[i] : bk[i - CD];
}

// ---------------- gather entity span features: g_efea[bt*E+e][h] ----------------
__global__ void gather_efea_kernel(const float* __restrict__ xs, const int* __restrict__ spans) {
    int i4 = blockIdx.x * blockDim.x + threadIdx.x;        // over 256*768/4
    if (i4 >= CB * CT * CE * CH / 4) return;
    int f = i4 * 4;
    int row = f / CH, c = f % CH;
    int bt = row >> 3, e = row & 7;
    int b = bt >> 1;
    int span = spans[bt];
    *reinterpret_cast<float4*>(&g_efea[f]) =
        *reinterpret_cast<const float4*>(&xs[((long long)b * CS + span + e) * CH + c]);
}

// ---------------- feas = mean_e efea; wf = feas@Ww+bw; c1 = wf . Wa[0:A] ----------------
__global__ void feasC1_kernel(const float* __restrict__ Ww, const float* __restrict__ bw,
                              const float* __restrict__ Wa) {
    int bt = blockIdx.x;           // 32 blocks, 128 threads
    int tid = threadIdx.x;
    __shared__ float s_f[CH];
    __shared__ float s_r[4];
    for (int h = tid; h < CH; h += 128) {
        float a = 0.f;
        #pragma unroll
        for (int e = 0; e < CE; e++) a += g_efea[(bt * CE + e) * CH + h];
        s_f[h] = a * (1.0f / CE);
    }
    __syncthreads();
    float acc = bw[tid];
    for (int h = 0; h < CH; h++) acc += s_f[h] * Ww[h * CA + tid];
    float part = acc * Wa[tid];
    #pragma unroll
    for (int off = 16; off; off >>= 1) part += __shfl_xor_sync(0xffffffffu, part, off);
    if ((tid & 31) == 0) s_r[tid >> 5] = part;
    __syncthreads();
    if (tid == 0) g_c1[bt] = s_r[0] + s_r[1] + s_r[2] + s_r[3];
}

// ---------------- stage B: per-neighbor SDPA + messages + score ----------------
__global__ void stageB_kernel(const float* __restrict__ neigh, const float* __restrict__ dists,
                              const float* __restrict__ Ww, const float* __restrict__ bw,
                              const float* __restrict__ Wa, const float* __restrict__ ba,
                              const float* __restrict__ wb, const float* __restrict__ bb) {
    int bid = blockIdx.x;
    int bt = bid / CN, n = bid % CN;
    int tid = threadIdx.x;
    const float inv_sqrt_d = 0.08838834764831845f;

    __shared__ float s_q[CE][CD];
    __shared__ float s_kc[CL][CD + 1];
    __shared__ float s_attn[CE][CL];
    __shared__ float s_pooled[CH];
    __shared__ float s_red[256];

    for (int i = tid; i < CE * CD; i += 256) s_q[i / CD][i % CD] = g_qe[bt * CE * CD + i];
    const long long kb = ((long long)bid) * CL * CD;
    for (int i = tid; i < CL * CD; i += 256) {
        int l = i >> 7, d = i & 127;
        s_kc[l][d] = g_kbuf[kb + i];
    }
    __syncthreads();

    for (int o = tid; o < CE * CL; o += 256) {
        int e = o / CL, l = o % CL;
        float acc = 0.f;
        #pragma unroll 8
        for (int d = 0; d < CD; d++) acc += s_q[e][d] * s_kc[l][d];
        s_attn[e][l] = acc * inv_sqrt_d;
    }
    __syncthreads();

    {
        int w = tid >> 5, lane = tid & 31;
        if (w < CE) {
            float v1 = s_attn[w][lane], v2 = s_attn[w][lane + 32];
            float m = fmaxf(v1, v2);
            #pragma unroll
            for (int off = 16; off; off >>= 1) m = fmaxf(m, __shfl_xor_sync(0xffffffffu, m, off));
            float e1 = __expf(v1 - m), e2 = __expf(v2 - m);
            float s = e1 + e2;
            #pragma unroll
            for (int off = 16; off; off >>= 1) s += __shfl_xor_sync(0xffffffffu, s, off);
            float inv = 1.0f / s;
            s_attn[w][lane] = e1 * inv;
            s_attn[w][lane + 32] = e2 * inv;
        }
    }
    __syncthreads();

    const long long nb = ((long long)bid) * CL * CH;
    const long long mb = ((long long)bid) * CE * CH;
    for (int hc = 0; hc < CH; hc += 128) {
        for (int i = tid; i < CL * 128; i += 256) {
            int l = i >> 7, j = i & 127;
            s_kc[l][j] = neigh[nb + (long long)l * CH + hc + j];
        }
        __syncthreads();
        float local = 0.f;
        #pragma unroll
        for (int rep = 0; rep < 4; rep++) {
            int o = tid + rep * 256;
            int e = o >> 7, j = o & 127;
            float acc = 0.f;
            #pragma unroll 8
            for (int l = 0; l < CL; l++) acc += s_attn[e][l] * s_kc[l][j];
            g_msgs[mb + (long long)e * CH + hc + j] = acc;
            local += acc;
        }
        s_red[tid] = local;
        __syncthreads();
        if (tid < 128) s_pooled[hc + tid] = (s_red[tid] + s_red[tid + 128]) * (1.0f / CE);
        __syncthreads();
    }

    float part = 0.f;
    if (tid < CA) {
        float acc = bw[tid];
        for (int h = 0; h < CH; h++) acc += s_pooled[h] * Ww[h * CA + tid];
        part = acc * Wa[CA + tid];
    }
    s_red[tid] = part;
    __syncthreads();
    for (int s = 128; s > 0; s >>= 1) {
        if (tid < s) s_red[tid] += s_red[tid + s];
        __syncthreads();
    }
    if (tid == 0) {
        float v = g_c1[bt] + s_red[0] + ba[0];
        v = (v > 0.f) ? v : 0.01f * v;
        v += dists[bt * CN + n] * wb[0] + bb[0];
        g_score[bt * CN + n] = 1.0f / (1.0f + __expf(-v));
    }
}

// ---------------- copy xs -> x ----------------
__global__ void copy_kernel(const float* __restrict__ xs) {
    long long i = (long long)blockIdx.x * blockDim.x + threadIdx.x;
    const long long n4 = (long long)CB * CS * CH / 4;
    if (i < n4) reinterpret_cast<float4*>(g_x)[i] = reinterpret_cast<const float4*>(xs)[i];
}

// ---------------- scatter delta into spans (one t per launch) ----------------
__global__ void scatter_kernel(const int* __restrict__ spans, int t) {
    int i = blockIdx.x * blockDim.x + threadIdx.x;
    if (i >= CB * CE * CH) return;
    int b = i / (CE * CH);
    int r = i % (CE * CH);
    int e = r / CH, h = r % CH;
    int bt = b * CT + t;
    float val = 0.f;
    const float* sc = &g_score[bt * CN];
    const float* ms = &g_msgs[(((long long)bt * CN) * CE + e) * CH + h];
    #pragma unroll 8
    for (int n = 0; n < CN; n++) val += sc[n] * ms[(long long)n * CE * CH];
    int span = spans[bt];
    g_x[((long long)b * CS + span + e) * CH + h] += val;
}

// ---------------- row softmax for s2 ----------------
__global__ void softmax_kernel() {
    int row = blockIdx.x;
    int tid = threadIdx.x;
    float* p = &g_s2[(long long)row * CS];
    __shared__ float s_red[256];
    float v1 = p[tid], v2 = p[tid + 256];
    float m = fmaxf(v1, v2);
    s_red[tid] = m;
    __syncthreads();
    for (int s = 128; s > 0; s >>= 1) { if (tid < s) s_red[tid] = fmaxf(s_red[tid], s_red[tid + s]); __syncthreads(); }
    m = s_red[0];
    __syncthreads();
    float e1 = __expf(v1 - m), e2 = __expf(v2 - m);
    s_red[tid] = e1 + e2;
    __syncthreads();
    for (int s = 128; s > 0; s >>= 1) { if (tid < s) s_red[tid] += s_red[tid + s]; __syncthreads(); }
    float inv = 1.0f / s_red[0];
    p[tid] = e1 * inv;
    p[tid + 256] = e2 * inv;
}

// ---------------- host ----------------
extern "C" void kernel_launch(void* const* d_in, const int* in_sizes, int n_in,
                              void* d_out, int out_size) {
    const float* xs    = (const float*)d_in[0];
    const float* neigh = (const float*)d_in[1];
    const float* dists = (const float*)d_in[2];
    const int*   spans = (const int*)d_in[3];
    const float* Wq = (const float*)d_in[4];
    const float* bq = (const float*)d_in[5];
    const float* Wk = (const float*)d_in[6];
    const float* bk = (const float*)d_in[7];
    const float* Wv = (const float*)d_in[8];
    const float* bv = (const float*)d_in[9];
    const float* Ww = (const float*)d_in[10];
    const float* bw = (const float*)d_in[11];
    const float* Wa = (const float*)d_in[12];
    const float* ba = (const float*)d_in[13];
    const float* wb = (const float*)d_in[14];
    const float* bb = (const float*)d_in[15];
    float* out = (float*)d_out;

    float *kbuf, *x, *qk2, *v2T, *s2, *wqkT, *wvT, *bqk, *efea, *qe;
    cudaGetSymbolAddress((void**)&kbuf, g_kbuf);
    cudaGetSymbolAddress((void**)&x,    g_x);
    cudaGetSymbolAddress((void**)&qk2,  g_qk2);
    cudaGetSymbolAddress((void**)&v2T,  g_v2T);
    cudaGetSymbolAddress((void**)&s2,   g_s2);
    cudaGetSymbolAddress((void**)&wqkT, g_wqkT);
    cudaGetSymbolAddress((void**)&wvT,  g_wvT);
    cudaGetSymbolAddress((void**)&bqk,  g_bqk);
    cudaGetSymbolAddress((void**)&efea, g_efea);
    cudaGetSymbolAddress((void**)&qe,   g_qe);

    cudaFuncSetAttribute(mm_gemm_kernel, cudaFuncAttributeMaxDynamicSharedMemorySize, GE_SMEM_BYTES);

    const float inv_sqrt_d = 0.08838834764831845f;
    dim3 tb(32, 8);

    // weight prep: wqkT = [WqT; WkT], wvT = Wv^T, bqk = [bq; bk]
    transpose_kernel<<<dim3(4, 24), tb>>>(Wq, wqkT, CH, CD);
    transpose_kernel<<<dim3(4, 24), tb>>>(Wk, wqkT + CD * CH, CH, CD);
    transpose_kernel<<<dim3(24, 24), tb>>>(Wv, wvT, CH, CH);
    pack_bqk_kernel<<<1, 2 * CD>>>(bq, bk);

    // entity features -> q (via tensor GEMM), feas/c1
    gather_efea_kernel<<<(CB*CT*CE*CH/4 + 255) / 256, 256>>>(xs, spans);
    mm_gemm_kernel<<<dim3(1, 2, 1), 256, GE_SMEM_BYTES>>>(
        efea, wqkT, bq, qe, CB*CT*CE, CD, CH, 1.0f, CH, CH, CD, 1, 0, 0, 0);
    feasC1_kernel<<<CB * CT, 128>>>(Ww, bw, Wa);

    // k projection: [65536,768] @ WkT^T -> [65536,128]
    mm_gemm_kernel<<<dim3(1, 512, 1), 256, GE_SMEM_BYTES>>>(
        neigh, wqkT + CD * CH, bk, kbuf, CB*CT*CN*CL, CD, CH, 1.0f, CH, CH, CD, 1, 0, 0, 0);

    // per-neighbor SDPA + messages + scores
    stageB_kernel<<<CB * CT * CN, 256>>>(neigh, dists, Ww, bw, Wa, ba, wb, bb);

    // x = xs; scatter deltas (t=0, t=1 sequential: deterministic)
    copy_kernel<<<(CB * CS * CH / 4 + 255) / 256, 256>>>(xs);
    scatter_kernel<<<(CB * CE * CH + 255) / 256, 256>>>(spans, 0);
    scatter_kernel<<<(CB * CE * CH + 255) / 256, 256>>>(spans, 1);

    // fused q2|k2 projection: [8192,768] @ wqkT^T -> [8192,256]
    mm_gemm_kernel<<<dim3(2, 64, 1), 256, GE_SMEM_BYTES>>>(
        x, wqkT, bqk, qk2, CB * CS, 2 * CD, CH, 1.0f, CH, CH, 2 * CD, 1, 0, 0, 0);

    // v2T = wvT @ x^T per batch: [768,512], row-bias bv
    mm_gemm_kernel<<<dim3(4, 6, CB), 256, GE_SMEM_BYTES>>>(
        wvT, x, bv, v2T, CH, CS, CH, 1.0f, CH, CH, CS, 2,
        0, (long long)CS * CH, (long long)CH * CS);

    // s2 = q2 @ k2^T * inv_sqrt_d (batched; q2/k2 interleaved in qk2)
    mm_gemm_kernel<<<dim3(4, 4, CB), 256, GE_SMEM_BYTES>>>(
        qk2, qk2 + CD, nullptr, s2, CS, CS, CD, inv_sqrt_d, 2 * CD, 2 * CD, CS, 0,
        (long long)CS * 2 * CD, (long long)CS * 2 * CD, (long long)CS * CS);

    softmax_kernel<<<CB * CS, 256>>>();

    // out = softmax(s2) @ v2  (B operand = v2T [768,512], batched)
    mm_gemm_kernel<<<dim3(6, 4, CB), 256, GE_SMEM_BYTES>>>(
        s2, v2T, nullptr, out, CS, CH, CS, 1.0f, CS, CS, CH, 0,
        (long long)CS * CS, (long long)CH * CS, (long long)CS * CH);
}